// round 4
// baseline (speedup 1.0000x reference)
#include <cuda_runtime.h>
#include <math.h>
#include <stdint.h>

// ---------------- scratch (allocation-free: __device__ globals) ----------------
__device__ __align__(1024) float g_hidden[32768ULL * 512];    // [N, 512]
__device__ __align__(1024) float g_params[32768ULL * 1792];   // [N, 1792]

#define BVAL   3.0f
#define KBINS  5
#define MIN_BW 0.001f
#define MIN_BH 0.001f
#define MIN_DV 0.001f

// ======================= helpers =======================
// 3xTF32 split: x = big + small (both tf32-representable)
__device__ __forceinline__ void split_tf32(float x, uint32_t& big, uint32_t& sml) {
    asm("cvt.rna.tf32.f32 %0, %1;" : "=r"(big) : "f"(x));
    float r = x - __uint_as_float(big);
    asm("cvt.rna.tf32.f32 %0, %1;" : "=r"(sml) : "f"(r));
}

__device__ __forceinline__ void mma_tf32(float* d, const uint32_t* a, uint32_t b0, uint32_t b1) {
    asm volatile(
        "mma.sync.aligned.m16n8k8.row.col.f32.tf32.tf32.f32 "
        "{%0,%1,%2,%3}, {%4,%5,%6,%7}, {%8,%9}, {%0,%1,%2,%3};"
        : "+f"(d[0]), "+f"(d[1]), "+f"(d[2]), "+f"(d[3])
        : "r"(a[0]), "r"(a[1]), "r"(a[2]), "r"(a[3]), "r"(b0), "r"(b1));
}

// ======================= 3xTF32 tensor-core GEMM =======================
// C[rows x M] = act(A[rows x K] @ B[K x M] + bias), all fp32 row-major.
// Block tile 128x128, BK=32, 256 threads (8 warps, 2x4), warp tile 64x32.
// smem holds RAW fp32; the tf32 big/small split happens in registers, so
// each product is computed as Ab*Bb + As*Bb + Ab*Bs (3 MMAs, ~1e-6 rel err).
// smem layout: element (r, k) of a 128x32 tile stored at
//   [r*32 + (((k&3)<<3 | (k>>2)) ^ ((r&3)<<1))]
// so each lane's mma fragment is a contiguous float2.
template <int ACT>
__global__ void __launch_bounds__(256) gemm_mma(
    const float* __restrict__ A, int lda,
    const float* __restrict__ B,          // [K, M] row-major (weights, untransposed)
    const float* __restrict__ bias,
    float* __restrict__ C, int M, int K)
{
    __shared__ float As[128 * 32];
    __shared__ float Bs[128 * 32];

    const int tid  = threadIdx.x;
    const int lane = tid & 31;
    const int wid  = tid >> 5;
    const int warp_m = wid & 1;        // 0..1  (64 rows each)
    const int warp_n = wid >> 1;       // 0..3  (32 cols each)
    const int rowBase = blockIdx.y * 128;
    const int colBase = blockIdx.x * 128;

    // staging thread mapping
    const int ar = tid >> 1;           // A row within tile: 0..127
    const int ak = (tid & 1) * 16;     // A k base: 0 or 16
    const int bk = tid >> 3;           // B k within chunk: 0..31
    const int bc = (tid & 7) * 16;     // B col base: 0..112

    const float* Ag = A + (size_t)(rowBase + ar) * lda + ak;
    const float* Bg = B + (size_t)bk * M + colBase + bc;

    float4 aReg[4], bReg[4];
#pragma unroll
    for (int q = 0; q < 4; q++) {
        aReg[q] = *(const float4*)(Ag + 4 * q);
        bReg[q] = *(const float4*)(Bg + 4 * q);
    }

    float acc[4][4][4];
#pragma unroll
    for (int mt = 0; mt < 4; mt++)
#pragma unroll
        for (int nt = 0; nt < 4; nt++)
#pragma unroll
            for (int c = 0; c < 4; c++) acc[mt][nt][c] = 0.f;

    const int nIter = K >> 5;
    for (int it = 0; it < nIter; it++) {
        // ---- stage registers -> smem (raw fp32, permuted+swizzled) ----
#pragma unroll
        for (int q = 0; q < 4; q++) {
            float av[4] = { aReg[q].x, aReg[q].y, aReg[q].z, aReg[q].w };
            float bv[4] = { bReg[q].x, bReg[q].y, bReg[q].z, bReg[q].w };
#pragma unroll
            for (int i = 0; i < 4; i++) {
                int k = ak + 4 * q + i;
                int idx = (((k & 3) << 3) | (k >> 2)) ^ ((ar & 3) << 1);
                As[ar * 32 + idx] = av[i];
                int col = bc + 4 * q + i;
                int idx2 = (((bk & 3) << 3) | (bk >> 2)) ^ ((col & 3) << 1);
                Bs[col * 32 + idx2] = bv[i];
            }
        }
        __syncthreads();

        // ---- prefetch next chunk ----
        if (it + 1 < nIter) {
            const float* An = Ag + (it + 1) * 32;
            const float* Bn = Bg + (size_t)(it + 1) * 32 * M;
#pragma unroll
            for (int q = 0; q < 4; q++) {
                aReg[q] = *(const float4*)(An + 4 * q);
                bReg[q] = *(const float4*)(Bn + 4 * q);
            }
        }

        // ---- compute 4 k-steps ----
#pragma unroll
        for (int ks = 0; ks < 4; ks++) {
            const int fidx = ((lane & 3) << 3) + ks * 2;
            uint32_t abig[4][4], asml[4][4];
#pragma unroll
            for (int mt = 0; mt < 4; mt++) {
                int r0 = warp_m * 64 + mt * 16 + (lane >> 2);
                int r1 = r0 + 8;
                float2 lo = *(const float2*)&As[r0 * 32 + (fidx ^ ((r0 & 3) << 1))];
                float2 hi = *(const float2*)&As[r1 * 32 + (fidx ^ ((r1 & 3) << 1))];
                split_tf32(lo.x, abig[mt][0], asml[mt][0]);
                split_tf32(hi.x, abig[mt][1], asml[mt][1]);
                split_tf32(lo.y, abig[mt][2], asml[mt][2]);
                split_tf32(hi.y, abig[mt][3], asml[mt][3]);
            }
#pragma unroll
            for (int nt = 0; nt < 4; nt++) {
                int c = warp_n * 32 + nt * 8 + (lane >> 2);
                float2 bb = *(const float2*)&Bs[c * 32 + (fidx ^ ((c & 3) << 1))];
                uint32_t bb0, bs0, bb1, bs1;
                split_tf32(bb.x, bb0, bs0);
                split_tf32(bb.y, bb1, bs1);
#pragma unroll
                for (int mt = 0; mt < 4; mt++) {
                    mma_tf32(acc[mt][nt], asml[mt], bb0, bb1);   // As*Bb
                    mma_tf32(acc[mt][nt], abig[mt], bs0, bs1);   // Ab*Bs
                    mma_tf32(acc[mt][nt], abig[mt], bb0, bb1);   // Ab*Bb
                }
            }
        }
        __syncthreads();
    }

    // ---- epilogue: bias (+tanh), store ----
#pragma unroll
    for (int mt = 0; mt < 4; mt++) {
#pragma unroll
        for (int nt = 0; nt < 4; nt++) {
            int row = rowBase + warp_m * 64 + mt * 16 + (lane >> 2);
            int col = colBase + warp_n * 32 + nt * 8 + (lane & 3) * 2;
            float b0 = bias[col], b1 = bias[col + 1];
            float v0 = acc[mt][nt][0] + b0, v1 = acc[mt][nt][1] + b1;
            float v2 = acc[mt][nt][2] + b0, v3 = acc[mt][nt][3] + b1;
            if (ACT == 1) { v0 = tanhf(v0); v1 = tanhf(v1); v2 = tanhf(v2); v3 = tanhf(v3); }
            *(float2*)&C[(size_t)row * M + col]       = make_float2(v0, v1);
            *(float2*)&C[(size_t)(row + 8) * M + col] = make_float2(v2, v3);
        }
    }
}

// ======================= spline =======================
__device__ __forceinline__ float softplusf(float x) {
    return (x > 20.0f) ? x : log1pf(expf(x));
}

__global__ void __launch_bounds__(128) spline_kernel(
    const float* __restrict__ xin, int xoff,
    const float* __restrict__ params,
    float* __restrict__ z, int zoff,
    float* __restrict__ logdet, int add)
{
    const int n = blockIdx.x;
    const int d = threadIdx.x;

    const float* p = params + (size_t)n * 1792 + d * 14;
    float raw[14];
#pragma unroll
    for (int j = 0; j < 14; j++) raw[j] = p[j];

    const float t = xin[(size_t)n * 256 + xoff + d];

    float cw[6], wd[5];
    {
        float m = raw[0];
#pragma unroll
        for (int j = 1; j < 5; j++) m = fmaxf(m, raw[j]);
        float e[5], s = 0.f;
#pragma unroll
        for (int j = 0; j < 5; j++) { e[j] = expf(raw[j] - m); s += e[j]; }
        float Wu[5];
#pragma unroll
        for (int j = 0; j < 5; j++) Wu[j] = 2.0f * BVAL * e[j] / s;
        float m2 = Wu[0];
#pragma unroll
        for (int j = 1; j < 5; j++) m2 = fmaxf(m2, Wu[j]);
        float e2[5], s2 = 0.f;
#pragma unroll
        for (int j = 0; j < 5; j++) { e2[j] = expf(Wu[j] - m2); s2 += e2[j]; }
        cw[0] = -BVAL;
        float run = 0.f;
#pragma unroll
        for (int j = 0; j < 5; j++) {
            float w = MIN_BW + (1.0f - MIN_BW * KBINS) * (e2[j] / s2);
            run += w;
            cw[j + 1] = 2.0f * BVAL * run - BVAL;
        }
        cw[5] = BVAL;
#pragma unroll
        for (int j = 0; j < 5; j++) wd[j] = cw[j + 1] - cw[j];
    }

    float ch[6], hd[5];
    {
        float m = raw[5];
#pragma unroll
        for (int j = 1; j < 5; j++) m = fmaxf(m, raw[5 + j]);
        float e[5], s = 0.f;
#pragma unroll
        for (int j = 0; j < 5; j++) { e[j] = expf(raw[5 + j] - m); s += e[j]; }
        float Hu[5];
#pragma unroll
        for (int j = 0; j < 5; j++) Hu[j] = 2.0f * BVAL * e[j] / s;
        float m2 = Hu[0];
#pragma unroll
        for (int j = 1; j < 5; j++) m2 = fmaxf(m2, Hu[j]);
        float e2[5], s2 = 0.f;
#pragma unroll
        for (int j = 0; j < 5; j++) { e2[j] = expf(Hu[j] - m2); s2 += e2[j]; }
        ch[0] = -BVAL;
        float run = 0.f;
#pragma unroll
        for (int j = 0; j < 5; j++) {
            float h = MIN_BH + (1.0f - MIN_BH * KBINS) * (e2[j] / s2);
            run += h;
            ch[j + 1] = 2.0f * BVAL * run - BVAL;
        }
        ch[5] = BVAL;
#pragma unroll
        for (int j = 0; j < 5; j++) hd[j] = ch[j + 1] - ch[j];
    }

    float deriv[6];
    deriv[0] = 1.0f;
    deriv[5] = 1.0f;
#pragma unroll
    for (int j = 0; j < 4; j++) {
        float du = softplusf(raw[10 + j]);
        deriv[j + 1] = MIN_DV + softplusf(du);
    }

    const float xc = fminf(fmaxf(t, -BVAL), BVAL);
    int cnt = 0;
#pragma unroll
    for (int j = 0; j < 6; j++) cnt += (xc >= cw[j]) ? 1 : 0;
    int idx = min(max(cnt - 1, 0), 4);

    const float icw = cw[idx], iw = wd[idx];
    const float ich = ch[idx], ih = hd[idx];
    const float delta = ih / iw;
    const float dk = deriv[idx], dk1 = deriv[idx + 1];
    const float theta = (xc - icw) / iw;
    const float t1m = theta * (1.0f - theta);
    const float num = ih * (delta * theta * theta + dk * t1m);
    const float den = delta + (dk + dk1 - 2.0f * delta) * t1m;
    const float y = ich + num / den;
    const float omt = 1.0f - theta;
    const float dnum = delta * delta * (dk1 * theta * theta + 2.0f * delta * t1m + dk * omt * omt);
    const float ld = logf(dnum) - 2.0f * logf(den);

    const bool inside = (t >= -BVAL) && (t <= BVAL);
    const float outv = inside ? y : t;
    const float ldv  = inside ? ld : 0.0f;

    z[(size_t)n * 256 + zoff + d] = outv;

    __shared__ float red[128];
    red[d] = ldv;
    __syncthreads();
#pragma unroll
    for (int s = 64; s > 0; s >>= 1) {
        if (d < s) red[d] += red[d + s];
        __syncthreads();
    }
    if (d == 0) {
        if (add) logdet[n] += red[0];
        else     logdet[n]  = red[0];
    }
}

// ======================= host side =======================
extern "C" void kernel_launch(void* const* d_in, const int* in_sizes, int n_in,
                              void* d_out, int out_size)
{
    const float* x     = (const float*)d_in[0];   // [N, 256]
    const float* f0_w0 = (const float*)d_in[1];   // [128, 512]
    const float* f0_b0 = (const float*)d_in[2];
    const float* f0_w1 = (const float*)d_in[3];   // [512, 1792]
    const float* f0_b1 = (const float*)d_in[4];
    const float* f1_w0 = (const float*)d_in[5];
    const float* f1_b0 = (const float*)d_in[6];
    const float* f1_w1 = (const float*)d_in[7];
    const float* f1_b1 = (const float*)d_in[8];

    const int N = in_sizes[0] / 256;              // 32768
    float* z      = (float*)d_out;                // [N, 256]
    float* logdet = z + (size_t)N * 256;          // [N]

    float* hidden = nullptr, *params = nullptr;
    cudaGetSymbolAddress((void**)&hidden, g_hidden);
    cudaGetSymbolAddress((void**)&params, g_params);

    const dim3 blk(256);
    const dim3 g1(512 / 128, N / 128);    // (4, 256)
    const dim3 g2(1792 / 128, N / 128);   // (14, 256)

    // ---- coupling 1: condition on x0 (cols 0..127), transform x1 ----
    gemm_mma<1><<<g1, blk>>>(x, 256, f0_w0, f0_b0, hidden, 512, 128);
    gemm_mma<0><<<g2, blk>>>(hidden, 512, f0_w1, f0_b1, params, 1792, 512);
    spline_kernel<<<N, 128>>>(x, 128, params, z, 128, logdet, 0);

    // ---- coupling 2: condition on new x1 (z cols 128..255), transform x0 ----
    gemm_mma<1><<<g1, blk>>>(z + 128, 256, f1_w0, f1_b0, hidden, 512, 128);
    gemm_mma<0><<<g2, blk>>>(hidden, 512, f1_w1, f1_b1, params, 1792, 512);
    spline_kernel<<<N, 128>>>(x, 0, params, z, 0, logdet, 1);
}

// round 5
// speedup vs baseline: 2.2719x; 2.2719x over previous
#include <cuda_runtime.h>
#include <cuda_bf16.h>
#include <math.h>
#include <stdint.h>

// ---------------- scratch (allocation-free: __device__ globals) ----------------
// split-bf16 pair-packed layout: word kpg of a row = bf16x2 of elements (2*kpg, 2*kpg+1),
// stored at position gidx(kpg) = (kpg & ~15) | ((kpg&3)<<2) | ((kpg>>2)&3)
__device__ __align__(1024) uint32_t g_xs_big[32768ULL * 64];
__device__ __align__(1024) uint32_t g_xs_sml[32768ULL * 64];
__device__ __align__(1024) uint32_t g_h_big[32768ULL * 256];
__device__ __align__(1024) uint32_t g_h_sml[32768ULL * 256];
__device__ __align__(1024) float    g_params[32768ULL * 1792];
__device__ __align__(1024) uint32_t g_w0b[2][512 * 64];
__device__ __align__(1024) uint32_t g_w0s[2][512 * 64];
__device__ __align__(1024) uint32_t g_w1b[2][1792 * 256];
__device__ __align__(1024) uint32_t g_w1s[2][1792 * 256];

#define BVAL   3.0f
#define KBINS  5
#define MIN_BW 0.001f
#define MIN_BH 0.001f
#define MIN_DV 0.001f

// ======================= helpers =======================
__device__ __forceinline__ int gidx(int kpg) {
    return (kpg & ~15) | ((kpg & 3) << 2) | ((kpg >> 2) & 3);
}

// split x into big+small bf16; pack pairs (x0 -> low half, x1 -> high half)
__device__ __forceinline__ void split2(float x0, float x1, uint32_t& b, uint32_t& s) {
    __nv_bfloat16 b0 = __float2bfloat16_rn(x0);
    __nv_bfloat16 b1 = __float2bfloat16_rn(x1);
    float r0 = x0 - __bfloat162float(b0);
    float r1 = x1 - __bfloat162float(b1);
    __nv_bfloat16 s0 = __float2bfloat16_rn(r0);
    __nv_bfloat16 s1 = __float2bfloat16_rn(r1);
    b = (uint32_t)__bfloat16_as_ushort(b0) | ((uint32_t)__bfloat16_as_ushort(b1) << 16);
    s = (uint32_t)__bfloat16_as_ushort(s0) | ((uint32_t)__bfloat16_as_ushort(s1) << 16);
}

__device__ __forceinline__ void mma_bf16(float* d,
                                         uint32_t a0, uint32_t a1, uint32_t a2, uint32_t a3,
                                         uint32_t b0, uint32_t b1) {
    asm volatile(
        "mma.sync.aligned.m16n8k16.row.col.f32.bf16.bf16.f32 "
        "{%0,%1,%2,%3}, {%4,%5,%6,%7}, {%8,%9}, {%0,%1,%2,%3};"
        : "+f"(d[0]), "+f"(d[1]), "+f"(d[2]), "+f"(d[3])
        : "r"(a0), "r"(a1), "r"(a2), "r"(a3), "r"(b0), "r"(b1));
}

__device__ __forceinline__ uint32_t smem_u32(const void* p) {
    uint32_t a;
    asm("{ .reg .u64 t; cvta.to.shared.u64 t, %1; cvt.u32.u64 %0, t; }" : "=r"(a) : "l"(p));
    return a;
}

#define CP16(dst, src) \
    asm volatile("cp.async.cg.shared.global [%0], [%1], 16;" :: "r"(dst), "l"(src) : "memory")
#define CP_COMMIT() asm volatile("cp.async.commit_group;" ::: "memory")
#define CP_WAIT1()  asm volatile("cp.async.wait_group 1;" ::: "memory")
#define CP_WAIT0()  asm volatile("cp.async.wait_group 0;" ::: "memory")

// ======================= converters =======================
// x [N,256] fp32 (col window xoff..xoff+127) -> split pair-packed [N,64] u32
__global__ void __launch_bounds__(256) conv_x(const float* __restrict__ x, int xoff,
                                              uint32_t* __restrict__ ob,
                                              uint32_t* __restrict__ os) {
    int t = blockIdx.x * 256 + threadIdx.x;
    int row = t >> 6, kpg = t & 63;
    float2 v = *(const float2*)(x + (size_t)row * 256 + xoff + 2 * kpg);
    uint32_t b, s;
    split2(v.x, v.y, b, s);
    int dst = row * 64 + gidx(kpg);
    ob[dst] = b; os[dst] = s;
}

// w [K, M] fp32 row-major -> transposed split pair-packed [M, K/2] u32
__global__ void __launch_bounds__(256) conv_w(const float* __restrict__ w, int M, int K2,
                                              uint32_t* __restrict__ ob,
                                              uint32_t* __restrict__ os) {
    __shared__ uint32_t tb[32][33], ts[32][33];
    const int m0 = blockIdx.x * 32, kp0 = blockIdx.y * 32;
    const int xx = threadIdx.x, yy = threadIdx.y;
    for (int i = yy; i < 32; i += 8) {
        int kpg = kp0 + i, m = m0 + xx;
        float v0 = w[(size_t)(2 * kpg) * M + m];
        float v1 = w[(size_t)(2 * kpg + 1) * M + m];
        split2(v0, v1, tb[i][xx], ts[i][xx]);
    }
    __syncthreads();
    for (int i = yy; i < 32; i += 8) {
        int m = m0 + i;
        size_t dst = (size_t)m * K2 + gidx(kp0 + xx);
        ob[dst] = tb[xx][i]; os[dst] = ts[xx][i];
    }
}

// ======================= bf16x3 tensor-core GEMM =======================
// C[rows x M] = act(A @ W + bias); A,W pre-split bf16 pair-packed (K2 = K/2 words/row).
// Block tile 128x128, BK = 16 words (32 k), 256 threads (8 warps 2x4), warp 64x32.
// cp.async double-buffered. 3-term: Ab*Bb + As*Bb + Ab*Bs.
// EPI 0: fp32 store (+bias). EPI 1: tanh then split-bf16 store to Hb/Hs.
#define GEMM_SMEM (2 * 32768)

template <int EPI>
__global__ void __launch_bounds__(256, 2) gemm_bf16x3(
    const uint32_t* __restrict__ Ab, const uint32_t* __restrict__ As,
    const uint32_t* __restrict__ Bb, const uint32_t* __restrict__ Bs,
    const float* __restrict__ bias,
    float* __restrict__ C, uint32_t* __restrict__ Hb, uint32_t* __restrict__ Hs,
    int M, int K2)
{
    extern __shared__ uint32_t sm[];
    const uint32_t sbase = smem_u32(sm);
    const int tid  = threadIdx.x;
    const int lane = tid & 31;
    const int wid  = tid >> 5;
    const int warp_m = wid & 1;
    const int warp_n = wid >> 1;
    const int rowBase = blockIdx.y * 128;
    const int colBase = blockIdx.x * 128;
    const int q  = lane & 3;
    const int rw = lane >> 2;

    // cp.async staging: thread covers row (tid>>1), 32B half (tid&1)
    const int cr  = tid >> 1;
    const int cw8 = (tid & 1) * 8;
    const uint32_t* gAb = Ab + (size_t)(rowBase + cr) * K2 + cw8;
    const uint32_t* gAs = As + (size_t)(rowBase + cr) * K2 + cw8;
    const uint32_t* gBb = Bb + (size_t)(colBase + cr) * K2 + cw8;
    const uint32_t* gBs = Bs + (size_t)(colBase + cr) * K2 + cw8;
    const uint32_t sdst = sbase + (uint32_t)(cr * 16 + cw8) * 4;

    // stage layout (words): Ab 0, As 2048, Bb 4096, Bs 6144; stage stride 8192
#define STAGE(it, buf) do { \
        uint32_t d0 = sdst + (buf) * 32768u; \
        const uint32_t* pa = gAb + (it) * 16; \
        const uint32_t* ps = gAs + (it) * 16; \
        const uint32_t* pb = gBb + (it) * 16; \
        const uint32_t* pq = gBs + (it) * 16; \
        CP16(d0,          pa); CP16(d0 + 16,          pa + 4); \
        CP16(d0 + 8192,   ps); CP16(d0 + 8192 + 16,   ps + 4); \
        CP16(d0 + 16384,  pb); CP16(d0 + 16384 + 16,  pb + 4); \
        CP16(d0 + 24576,  pq); CP16(d0 + 24576 + 16,  pq + 4); \
        CP_COMMIT(); \
    } while (0)

    float acc[4][4][4];
#pragma unroll
    for (int mt = 0; mt < 4; mt++)
#pragma unroll
        for (int nt = 0; nt < 4; nt++)
#pragma unroll
            for (int c = 0; c < 4; c++) acc[mt][nt][c] = 0.f;

    const int nIter = K2 >> 4;
    STAGE(0, 0);

    for (int it = 0; it < nIter; it++) {
        const int buf = it & 1;
        if (it + 1 < nIter) { STAGE(it + 1, buf ^ 1); CP_WAIT1(); }
        else                { CP_WAIT0(); }
        __syncthreads();

        const uint32_t* sA = sm + buf * 8192;
        const uint32_t* sB = sA + 4096;

        // B fragments for the whole BK chunk (both ks, big+small)
        uint4 bbig[4], bsml[4];
#pragma unroll
        for (int nt = 0; nt < 4; nt++) {
            const uint32_t* p = sB + (warp_n * 32 + nt * 8 + rw) * 16 + 4 * q;
            bbig[nt] = *(const uint4*)p;
            bsml[nt] = *(const uint4*)(p + 2048);
        }

#pragma unroll
        for (int mt = 0; mt < 4; mt++) {
            const uint32_t* p = sA + (warp_m * 64 + mt * 16 + rw) * 16 + 4 * q;
            uint4 alo = *(const uint4*)p;
            uint4 ahi = *(const uint4*)(p + 128);
            uint4 slo = *(const uint4*)(p + 2048);
            uint4 shi = *(const uint4*)(p + 2048 + 128);
            // term 1: Ab*Bb (ks0 then ks1)
#pragma unroll
            for (int nt = 0; nt < 4; nt++)
                mma_bf16(acc[mt][nt], alo.x, ahi.x, alo.y, ahi.y, bbig[nt].x, bbig[nt].y);
#pragma unroll
            for (int nt = 0; nt < 4; nt++)
                mma_bf16(acc[mt][nt], alo.z, ahi.z, alo.w, ahi.w, bbig[nt].z, bbig[nt].w);
            // term 2: As*Bb
#pragma unroll
            for (int nt = 0; nt < 4; nt++)
                mma_bf16(acc[mt][nt], slo.x, shi.x, slo.y, shi.y, bbig[nt].x, bbig[nt].y);
#pragma unroll
            for (int nt = 0; nt < 4; nt++)
                mma_bf16(acc[mt][nt], slo.z, shi.z, slo.w, shi.w, bbig[nt].z, bbig[nt].w);
            // term 3: Ab*Bs
#pragma unroll
            for (int nt = 0; nt < 4; nt++)
                mma_bf16(acc[mt][nt], alo.x, ahi.x, alo.y, ahi.y, bsml[nt].x, bsml[nt].y);
#pragma unroll
            for (int nt = 0; nt < 4; nt++)
                mma_bf16(acc[mt][nt], alo.z, ahi.z, alo.w, ahi.w, bsml[nt].z, bsml[nt].w);
        }
        __syncthreads();
    }

    // ---- epilogue ----
#pragma unroll
    for (int mt = 0; mt < 4; mt++) {
#pragma unroll
        for (int nt = 0; nt < 4; nt++) {
            int row = rowBase + warp_m * 64 + mt * 16 + rw;
            int col = colBase + warp_n * 32 + nt * 8 + q * 2;
            float b0 = bias[col], b1 = bias[col + 1];
            float v0 = acc[mt][nt][0] + b0, v1 = acc[mt][nt][1] + b1;
            float v2 = acc[mt][nt][2] + b0, v3 = acc[mt][nt][3] + b1;
            if (EPI == 1) {
                v0 = tanhf(v0); v1 = tanhf(v1); v2 = tanhf(v2); v3 = tanhf(v3);
                int kpg = col >> 1;
                int dcol = gidx(kpg);
                uint32_t bb, ss;
                split2(v0, v1, bb, ss);
                Hb[(size_t)row * (M >> 1) + dcol] = bb;
                Hs[(size_t)row * (M >> 1) + dcol] = ss;
                split2(v2, v3, bb, ss);
                Hb[(size_t)(row + 8) * (M >> 1) + dcol] = bb;
                Hs[(size_t)(row + 8) * (M >> 1) + dcol] = ss;
            } else {
                *(float2*)&C[(size_t)row * M + col]       = make_float2(v0, v1);
                *(float2*)&C[(size_t)(row + 8) * M + col] = make_float2(v2, v3);
            }
        }
    }
#undef STAGE
}

// ======================= spline =======================
__device__ __forceinline__ float softplusf(float x) {
    return (x > 20.0f) ? x : log1pf(expf(x));
}

__global__ void __launch_bounds__(128) spline_kernel(
    const float* __restrict__ xin, int xoff,
    const float* __restrict__ params,
    float* __restrict__ z, int zoff,
    float* __restrict__ logdet, int add)
{
    const int n = blockIdx.x;
    const int d = threadIdx.x;

    const float* p = params + (size_t)n * 1792 + d * 14;
    float raw[14];
#pragma unroll
    for (int j = 0; j < 14; j++) raw[j] = p[j];

    const float t = xin[(size_t)n * 256 + xoff + d];

    float cw[6], wd[5];
    {
        float m = raw[0];
#pragma unroll
        for (int j = 1; j < 5; j++) m = fmaxf(m, raw[j]);
        float e[5], s = 0.f;
#pragma unroll
        for (int j = 0; j < 5; j++) { e[j] = expf(raw[j] - m); s += e[j]; }
        float Wu[5];
#pragma unroll
        for (int j = 0; j < 5; j++) Wu[j] = 2.0f * BVAL * e[j] / s;
        float m2 = Wu[0];
#pragma unroll
        for (int j = 1; j < 5; j++) m2 = fmaxf(m2, Wu[j]);
        float e2[5], s2 = 0.f;
#pragma unroll
        for (int j = 0; j < 5; j++) { e2[j] = expf(Wu[j] - m2); s2 += e2[j]; }
        cw[0] = -BVAL;
        float run = 0.f;
#pragma unroll
        for (int j = 0; j < 5; j++) {
            float w = MIN_BW + (1.0f - MIN_BW * KBINS) * (e2[j] / s2);
            run += w;
            cw[j + 1] = 2.0f * BVAL * run - BVAL;
        }
        cw[5] = BVAL;
#pragma unroll
        for (int j = 0; j < 5; j++) wd[j] = cw[j + 1] - cw[j];
    }

    float ch[6], hd[5];
    {
        float m = raw[5];
#pragma unroll
        for (int j = 1; j < 5; j++) m = fmaxf(m, raw[5 + j]);
        float e[5], s = 0.f;
#pragma unroll
        for (int j = 0; j < 5; j++) { e[j] = expf(raw[5 + j] - m); s += e[j]; }
        float Hu[5];
#pragma unroll
        for (int j = 0; j < 5; j++) Hu[j] = 2.0f * BVAL * e[j] / s;
        float m2 = Hu[0];
#pragma unroll
        for (int j = 1; j < 5; j++) m2 = fmaxf(m2, Hu[j]);
        float e2[5], s2 = 0.f;
#pragma unroll
        for (int j = 0; j < 5; j++) { e2[j] = expf(Hu[j] - m2); s2 += e2[j]; }
        ch[0] = -BVAL;
        float run = 0.f;
#pragma unroll
        for (int j = 0; j < 5; j++) {
            float h = MIN_BH + (1.0f - MIN_BH * KBINS) * (e2[j] / s2);
            run += h;
            ch[j + 1] = 2.0f * BVAL * run - BVAL;
        }
        ch[5] = BVAL;
#pragma unroll
        for (int j = 0; j < 5; j++) hd[j] = ch[j + 1] - ch[j];
    }

    float deriv[6];
    deriv[0] = 1.0f;
    deriv[5] = 1.0f;
#pragma unroll
    for (int j = 0; j < 4; j++) {
        float du = softplusf(raw[10 + j]);
        deriv[j + 1] = MIN_DV + softplusf(du);
    }

    const float xc = fminf(fmaxf(t, -BVAL), BVAL);
    int cnt = 0;
#pragma unroll
    for (int j = 0; j < 6; j++) cnt += (xc >= cw[j]) ? 1 : 0;
    int idx = min(max(cnt - 1, 0), 4);

    const float icw = cw[idx], iw = wd[idx];
    const float ich = ch[idx], ih = hd[idx];
    const float delta = ih / iw;
    const float dk = deriv[idx], dk1 = deriv[idx + 1];
    const float theta = (xc - icw) / iw;
    const float t1m = theta * (1.0f - theta);
    const float num = ih * (delta * theta * theta + dk * t1m);
    const float den = delta + (dk + dk1 - 2.0f * delta) * t1m;
    const float y = ich + num / den;
    const float omt = 1.0f - theta;
    const float dnum = delta * delta * (dk1 * theta * theta + 2.0f * delta * t1m + dk * omt * omt);
    const float ld = logf(dnum) - 2.0f * logf(den);

    const bool inside = (t >= -BVAL) && (t <= BVAL);
    const float outv = inside ? y : t;
    const float ldv  = inside ? ld : 0.0f;

    z[(size_t)n * 256 + zoff + d] = outv;

    __shared__ float red[128];
    red[d] = ldv;
    __syncthreads();
#pragma unroll
    for (int s = 64; s > 0; s >>= 1) {
        if (d < s) red[d] += red[d + s];
        __syncthreads();
    }
    if (d == 0) {
        if (add) logdet[n] += red[0];
        else     logdet[n]  = red[0];
    }
}

// ======================= host side =======================
extern "C" void kernel_launch(void* const* d_in, const int* in_sizes, int n_in,
                              void* d_out, int out_size)
{
    const float* x     = (const float*)d_in[0];   // [N, 256]
    const float* f0_w0 = (const float*)d_in[1];   // [128, 512]
    const float* f0_b0 = (const float*)d_in[2];
    const float* f0_w1 = (const float*)d_in[3];   // [512, 1792]
    const float* f0_b1 = (const float*)d_in[4];
    const float* f1_w0 = (const float*)d_in[5];
    const float* f1_b0 = (const float*)d_in[6];
    const float* f1_w1 = (const float*)d_in[7];
    const float* f1_b1 = (const float*)d_in[8];

    const int N = in_sizes[0] / 256;              // 32768
    float* z      = (float*)d_out;                // [N, 256]
    float* logdet = z + (size_t)N * 256;          // [N]

    uint32_t *xsb, *xss, *hb, *hs, *w0b, *w0s, *w1b, *w1s;
    float* params;
    cudaGetSymbolAddress((void**)&xsb, g_xs_big);
    cudaGetSymbolAddress((void**)&xss, g_xs_sml);
    cudaGetSymbolAddress((void**)&hb,  g_h_big);
    cudaGetSymbolAddress((void**)&hs,  g_h_sml);
    cudaGetSymbolAddress((void**)&params, g_params);
    cudaGetSymbolAddress((void**)&w0b, g_w0b);
    cudaGetSymbolAddress((void**)&w0s, g_w0s);
    cudaGetSymbolAddress((void**)&w1b, g_w1b);
    cudaGetSymbolAddress((void**)&w1s, g_w1s);

    cudaFuncSetAttribute(gemm_bf16x3<0>, cudaFuncAttributeMaxDynamicSharedMemorySize, GEMM_SMEM);
    cudaFuncSetAttribute(gemm_bf16x3<1>, cudaFuncAttributeMaxDynamicSharedMemorySize, GEMM_SMEM);

    const dim3 tw(32, 8);
    // weight converters (4 small kernels)
    conv_w<<<dim3(512 / 32, 64 / 32), tw>>>(f0_w0, 512, 64, w0b, w0s);
    conv_w<<<dim3(1792 / 32, 256 / 32), tw>>>(f0_w1, 1792, 256, w1b, w1s);
    conv_w<<<dim3(512 / 32, 64 / 32), tw>>>(f1_w0, 512, 64, w0b + 512 * 64, w0s + 512 * 64);
    conv_w<<<dim3(1792 / 32, 256 / 32), tw>>>(f1_w1, 1792, 256, w1b + 1792 * 256, w1s + 1792 * 256);

    const dim3 g1(512 / 128, N / 128);    // (4, 256)
    const dim3 g2(1792 / 128, N / 128);   // (14, 256)
    const int nConvBlocks = N * 64 / 256; // 8192

    // ---- coupling 1: condition on x0 (cols 0..127), transform x1 ----
    conv_x<<<nConvBlocks, 256>>>(x, 0, xsb, xss);
    gemm_bf16x3<1><<<g1, 256, GEMM_SMEM>>>(xsb, xss, w0b, w0s, f0_b0,
                                           nullptr, hb, hs, 512, 64);
    gemm_bf16x3<0><<<g2, 256, GEMM_SMEM>>>(hb, hs, w1b, w1s, f0_b1,
                                           params, nullptr, nullptr, 1792, 256);
    spline_kernel<<<N, 128>>>(x, 128, params, z, 128, logdet, 0);

    // ---- coupling 2: condition on new x1 (z cols 128..255), transform x0 ----
    conv_x<<<nConvBlocks, 256>>>(z, 128, xsb, xss);
    gemm_bf16x3<1><<<g1, 256, GEMM_SMEM>>>(xsb, xss, w0b + 512 * 64, w0s + 512 * 64, f1_b0,
                                           nullptr, hb, hs, 512, 64);
    gemm_bf16x3<0><<<g2, 256, GEMM_SMEM>>>(hb, hs, w1b + 1792 * 256, w1s + 1792 * 256, f1_b1,
                                           params, nullptr, nullptr, 1792, 256);
    spline_kernel<<<N, 128>>>(x, 0, params, z, 0, logdet, 1);
}